// round 15
// baseline (speedup 1.0000x reference)
#include <cuda_runtime.h>
#include <cuda_bf16.h>
#include <math.h>
#include <stdint.h>

#define BB 2
#define TT 2048
#define DD 1024
#define HH 16
#define KNN 3
#define MM 16384
#define HDIM 64
#define NROWS (BB*TT)         // 4096
#define SCALE_F 4096.0f       // D * sqrt(H)
#define K3 3072               // split-concatenated K
#define PLANE (NROWS * DD)    // hi plane size; lo at +PLANE

// ---------------- scratch (static device globals; no runtime allocation) ----
__device__ float g_q[NROWS * DD];
__device__ float g_k[NROWS * DD];
__device__ float g_v[NROWS * DD];
__device__ float g_attn[NROWS * DD];
__device__ __nv_bfloat16 g_x2[NROWS * K3];       // split activations (reused for comb)
__device__ __nv_bfloat16 g_wqkv[4 * DD * K3];    // split Wq|Wk|Wv|Wo
__device__ __nv_bfloat16 g_qs[2 * PLANE];        // per-head (b,h,t,64) hi/lo
__device__ __nv_bfloat16 g_ks[2 * PLANE];
__device__ __nv_bfloat16 g_vs[2 * PLANE];

#define SWZ128(off) ((off) ^ (((off) >> 3) & 0x70))

__device__ __forceinline__ uint32_t smem_u32(const void* p) {
    uint32_t a;
    asm("{ .reg .u64 t; cvta.to.shared.u64 t, %1; cvt.u32.u64 %0, t; }"
        : "=r"(a) : "l"(p));
    return a;
}
__device__ __forceinline__ void cp_async16(uint32_t dst, const void* src) {
    asm volatile("cp.async.cg.shared.global [%0], [%1], 16;"
                 :: "r"(dst), "l"(src) : "memory");
}
__device__ __forceinline__ void cp_commit() {
    asm volatile("cp.async.commit_group;" ::: "memory");
}
__device__ __forceinline__ void ldm_x4(uint32_t* r, uint32_t addr) {
    asm volatile("ldmatrix.sync.aligned.m8n8.x4.shared.b16 {%0,%1,%2,%3}, [%4];"
                 : "=r"(r[0]), "=r"(r[1]), "=r"(r[2]), "=r"(r[3]) : "r"(addr));
}
__device__ __forceinline__ void ldm_x2(uint32_t* r, uint32_t addr) {
    asm volatile("ldmatrix.sync.aligned.m8n8.x2.shared.b16 {%0,%1}, [%2];"
                 : "=r"(r[0]), "=r"(r[1]) : "r"(addr));
}
__device__ __forceinline__ void ldm_x2t(uint32_t* r, uint32_t addr) {
    asm volatile("ldmatrix.sync.aligned.m8n8.x2.trans.shared.b16 {%0,%1}, [%2];"
                 : "=r"(r[0]), "=r"(r[1]) : "r"(addr));
}
__device__ __forceinline__ void mma16816(float* d, const uint32_t* a, const uint32_t* b) {
    asm volatile(
        "mma.sync.aligned.m16n8k16.row.col.f32.bf16.bf16.f32 "
        "{%0,%1,%2,%3}, {%4,%5,%6,%7}, {%8,%9}, {%0,%1,%2,%3};"
        : "+f"(d[0]), "+f"(d[1]), "+f"(d[2]), "+f"(d[3])
        : "r"(a[0]), "r"(a[1]), "r"(a[2]), "r"(a[3]), "r"(b[0]), "r"(b[1]));
}
__device__ __forceinline__ uint32_t packbf2(float lo, float hi) {
    uint32_t r;
    asm("cvt.rn.bf16x2.f32 %0, %1, %2;" : "=r"(r) : "f"(hi), "f"(lo));
    return r;
}

// ---------------------------------------------------------------------------
// One-shot split: x -> x2 [hi,hi,lo]; Wq/Wk/Wv/Wo -> wqkv slots [hi,lo,hi].
// ---------------------------------------------------------------------------
__global__ __launch_bounds__(256) void split_all_kernel(
    const float* __restrict__ x,
    const float* __restrict__ Wq, const float* __restrict__ Wk,
    const float* __restrict__ Wv, const float* __restrict__ Wo,
    __nv_bfloat16* __restrict__ x2, __nv_bfloat16* __restrict__ wqkv) {
    const int blk = blockIdx.x;
    const float* src;
    __nv_bfloat16* dstbase;
    int idx, modeB;
    if (blk < 16384) {
        src = x; dstbase = x2; modeB = 0;
        idx = blk * 256 + threadIdx.x;
    } else {
        const int t = blk - 16384;
        const int w = t >> 12;                 // 0..3
        src = (w == 0) ? Wq : (w == 1) ? Wk : (w == 2) ? Wv : Wo;
        dstbase = wqkv + (size_t)w * DD * K3;
        modeB = 1;
        idx = (t & 4095) * 256 + threadIdx.x;
    }
    const int row = idx >> 10, col = idx & 1023;
    float v = src[idx];
    __nv_bfloat16 h = __float2bfloat16(v);
    __nv_bfloat16 l = __float2bfloat16(v - __bfloat162float(h));
    __nv_bfloat16* y = dstbase + (size_t)row * K3 + col;
    y[0] = h;
    y[1024] = modeB ? l : h;
    y[2048] = modeB ? h : l;
}

// ---------------------------------------------------------------------------
// cp.async 3-stage bf16 HMMA GEMM, one sync per chunk, multi-output.
// stage s: A @ s*32768, B @ s*32768+16384.
// ---------------------------------------------------------------------------
#define GEMM_NCHUNK (K3 / 64)       // 48
#define GEMM_SMEM (3 * 32768)

__global__ __launch_bounds__(256) void gemm_mma_kernel(
    const __nv_bfloat16* __restrict__ A2, const __nv_bfloat16* __restrict__ B2,
    const float* __restrict__ bias0, const float* __restrict__ bias1,
    const float* __restrict__ bias2,
    float* __restrict__ C0, float* __restrict__ C1, float* __restrict__ C2) {
    extern __shared__ char smem[];
    const uint32_t s0 = smem_u32(smem);

    const int tid = threadIdx.x;
    const int wid = tid >> 5, lane = tid & 31;
    const int warpM = wid >> 2, warpN = wid & 3;
    const int bi = blockIdx.y * 128;
    const int gcol = blockIdx.x * 128;
    const int mat = gcol >> 10;
    const float* bias = (mat == 0) ? bias0 : (mat == 1) ? bias1 : bias2;
    float* C = (mat == 0) ? C0 : (mat == 1) ? C1 : C2;
    const int bj = gcol & 1023;

    const int rowL = tid >> 3;
    const int c16 = tid & 7;

    float acc[4][4][4];
#pragma unroll
    for (int i = 0; i < 4; i++)
#pragma unroll
        for (int j = 0; j < 4; j++)
#pragma unroll
            for (int r = 0; r < 4; r++) acc[i][j][r] = 0.f;

    const int aRow = warpM * 64 + (lane & 15);
    const int aHalf = (lane >> 4) * 16;
    const int bRow = warpN * 32 + (lane & 7);
    const int bHalf = ((lane >> 3) & 1) * 16;

    int soff[4];
#pragma unroll
    for (int i = 0; i < 4; i++)
        soff[i] = SWZ128((rowL + i * 32) * 128 + c16 * 16);
    const __nv_bfloat16* aSrc = A2 + (size_t)(bi + rowL) * K3 + c16 * 8;
    const __nv_bfloat16* bSrc = B2 + (size_t)(gcol + rowL) * K3 + c16 * 8;

#define GEMM_ISSUE(c, s) do {                                                  \
    const int _k0 = (c) * 64;                                                  \
    const uint32_t _da = s0 + (s) * 32768;                                     \
    const uint32_t _db = _da + 16384;                                          \
    _Pragma("unroll")                                                          \
    for (int _i = 0; _i < 4; _i++) {                                           \
        cp_async16(_da + soff[_i], aSrc + (size_t)_i * 32 * K3 + _k0);         \
        cp_async16(_db + soff[_i], bSrc + (size_t)_i * 32 * K3 + _k0);         \
    }                                                                          \
    cp_commit();                                                               \
} while (0)

    GEMM_ISSUE(0, 0);
    GEMM_ISSUE(1, 1);

    for (int c = 0; c < GEMM_NCHUNK; c++) {
        if (c + 1 < GEMM_NCHUNK)
            asm volatile("cp.async.wait_group 1;" ::: "memory");
        else
            asm volatile("cp.async.wait_group 0;" ::: "memory");
        __syncthreads();
        if (c + 2 < GEMM_NCHUNK) GEMM_ISSUE(c + 2, (c + 2) % 3);
        const int s = c % 3;
        const uint32_t sa = s0 + s * 32768;
        const uint32_t sb = sa + 16384;
#pragma unroll
        for (int st = 0; st < 4; st++) {
            uint32_t af[4][4], bf[4][2];
#pragma unroll
            for (int i = 0; i < 4; i++)
                ldm_x4(af[i], sa + SWZ128((aRow + i * 16) * 128 + st * 32 + aHalf));
#pragma unroll
            for (int j = 0; j < 4; j++)
                ldm_x2(bf[j], sb + SWZ128((bRow + j * 8) * 128 + st * 32 + bHalf));
#pragma unroll
            for (int i = 0; i < 4; i++)
#pragma unroll
                for (int j = 0; j < 4; j++)
                    mma16816(acc[i][j], af[i], bf[j]);
        }
    }
#undef GEMM_ISSUE

#pragma unroll
    for (int i = 0; i < 4; i++) {
        const int r0 = bi + warpM * 64 + i * 16 + (lane >> 2);
#pragma unroll
        for (int j = 0; j < 4; j++) {
            const int c0 = bj + warpN * 32 + j * 8 + (lane & 3) * 2;
            const float b0 = bias[c0], b1 = bias[c0 + 1];
            float2 o0 = make_float2(acc[i][j][0] + b0, acc[i][j][1] + b1);
            float2 o1 = make_float2(acc[i][j][2] + b0, acc[i][j][3] + b1);
            *(float2*)(C + (size_t)r0 * DD + c0) = o0;
            *(float2*)(C + (size_t)(r0 + 8) * DD + c0) = o1;
        }
    }
}

// ---------------------------------------------------------------------------
// Fused norm+split for q/k/v in one launch: grid (NROWS, 3).
// ---------------------------------------------------------------------------
__global__ __launch_bounds__(256) void norm_split_kernel(
    float* __restrict__ q, float* __restrict__ k, float* __restrict__ v,
    __nv_bfloat16* __restrict__ qs, __nv_bfloat16* __restrict__ ks,
    __nv_bfloat16* __restrict__ vs) {
    const int task = blockIdx.y;
    float* p = (task == 0) ? q : (task == 1) ? k : v;
    __nv_bfloat16* Y = (task == 0) ? qs : (task == 1) ? ks : vs;
    const int do_norm = (task < 2), writeback = (task == 0);

    const int row = blockIdx.x;
    const int b = row >> 11, t = row & 2047;
    const int tid = threadIdx.x;
    __shared__ float red[8];
    float4 a = *(const float4*)(p + (size_t)row * DD + tid * 4);
    if (do_norm) {
        float ss = a.x * a.x + a.y * a.y + a.z * a.z + a.w * a.w;
#pragma unroll
        for (int m = 16; m; m >>= 1) ss += __shfl_xor_sync(0xffffffffu, ss, m);
        if ((tid & 31) == 0) red[tid >> 5] = ss;
        __syncthreads();
        float tot = red[0] + red[1] + red[2] + red[3] +
                    red[4] + red[5] + red[6] + red[7];
        float inv = 1.0f / fmaxf(sqrtf(tot), 1e-12f);
        a.x *= inv; a.y *= inv; a.z *= inv; a.w *= inv;
        if (writeback)
            *(float4*)(p + (size_t)row * DD + tid * 4) = a;
    }
    const int h = tid >> 4;
    const int dh = (tid & 15) * 4;
    __nv_bfloat16* dst = Y + ((size_t)(b * HH + h) * TT + t) * 64 + dh;
    __nv_bfloat16 hi[4], lo[4];
    const float* av = (const float*)&a;
#pragma unroll
    for (int i = 0; i < 4; i++) {
        hi[i] = __float2bfloat16(av[i]);
        lo[i] = __float2bfloat16(av[i] - __bfloat162float(hi[i]));
    }
    *(uint2*)dst = *(const uint2*)hi;
    *(uint2*)(dst + PLANE) = *(const uint2*)lo;
}

// ---------------------------------------------------------------------------
// Flash attention via bf16 mma, hi/lo 3-term splits.
// Q fragments in registers; K/V cp.async 3-stage pipeline (3x32KB),
// ONE __syncthreads per iteration, issue before compute.
// stage s at s*32768: Kh +0, Kl +8192, Vh +16384, Vl +24576.
// ---------------------------------------------------------------------------
#define FLM_SMEM (3 * 32768)

__global__ __launch_bounds__(256, 2) void flash_mma_kernel(
    const __nv_bfloat16* __restrict__ qs, const __nv_bfloat16* __restrict__ ks,
    const __nv_bfloat16* __restrict__ vs, float* __restrict__ attn) {
    extern __shared__ char sm[];
    const uint32_t s0 = smem_u32(sm);

    const int qt = 15 - blockIdx.x;
    const int h = blockIdx.y, b = blockIdx.z;
    const int tid = threadIdx.x, wid = tid >> 5, lane = tid & 31;
    const size_t hb = ((size_t)(b * HH + h)) * TT * 64;

    // ---- prologue: load Q tile to smem, hoist fragments to registers ----
    {
        const int row = tid >> 1, part = tid & 1;
        const __nv_bfloat16* srcH = qs + hb + (size_t)(qt * 128 + row) * 64 + part * 32;
        const __nv_bfloat16* srcL = srcH + PLANE;
#pragma unroll
        for (int i = 0; i < 4; i++) {
            const int off = SWZ128(row * 128 + part * 64 + i * 16);
            *(uint4*)(sm + off) = *(const uint4*)(srcH + i * 8);
            *(uint4*)(sm + 16384 + off) = *(const uint4*)(srcL + i * 8);
        }
    }
    __syncthreads();
    uint32_t qh[4][4], ql[4][4];
    {
        const int qRow = wid * 16 + (lane & 15);
        const int qHalf = (lane >> 4) * 16;
#pragma unroll
        for (int s4 = 0; s4 < 4; s4++) {
            ldm_x4(qh[s4], s0 + SWZ128(qRow * 128 + s4 * 32 + qHalf));
            ldm_x4(ql[s4], s0 + 16384 + SWZ128(qRow * 128 + s4 * 32 + qHalf));
        }
    }
    __syncthreads();   // Q smem region now reusable by the K/V pipeline

    float out[8][4];
#pragma unroll
    for (int nt = 0; nt < 8; nt++)
#pragma unroll
        for (int r = 0; r < 4; r++) out[nt][r] = 0.f;
    float m0 = -1e30f, m1 = -1e30f, l0 = 0.f, l1 = 0.f;

    const int r4 = lane >> 2;
    const int cpair = (lane & 3) * 2;
    const int rowg0 = qt * 128 + wid * 16 + r4;
    const int rowg1 = rowg0 + 8;
    const int rowmax = qt * 128 + wid * 16 + 15;
    const int warpmin = qt * 128 + wid * 16;

    const int kRowL = lane & 7;
    const int kHalf = ((lane >> 3) & 1) * 16;
    const int vRowL = (lane & 7) + ((lane >> 3) & 1) * 8;

    // per-thread K/V cp.async slice
    const int ldRow = tid >> 2, ldC = tid & 3;
    const int d0 = SWZ128(ldRow * 128 + ldC * 32);
    const int d1 = SWZ128(ldRow * 128 + ldC * 32 + 16);
    const size_t srcOff0 = (size_t)ldRow * 64 + ldC * 16;

#define FL_ISSUE(kt_, s_) do {                                                 \
    const size_t _src = hb + (size_t)(kt_) * 64 * 64 + srcOff0;                \
    const uint32_t _b = s0 + (s_) * 32768;                                     \
    cp_async16(_b + d0,         ks + _src);                                    \
    cp_async16(_b + d1,         ks + _src + 8);                                \
    cp_async16(_b + 8192 + d0,  ks + PLANE + _src);                            \
    cp_async16(_b + 8192 + d1,  ks + PLANE + _src + 8);                        \
    cp_async16(_b + 16384 + d0, vs + _src);                                    \
    cp_async16(_b + 16384 + d1, vs + _src + 8);                                \
    cp_async16(_b + 24576 + d0, vs + PLANE + _src);                            \
    cp_async16(_b + 24576 + d1, vs + PLANE + _src + 8);                        \
    cp_commit();                                                               \
} while (0)

    const int ktmax = 2 * qt + 1;
    FL_ISSUE(0, 0);
    FL_ISSUE(1, 1);

    for (int kt = 0; kt <= ktmax; kt++) {
        const int j0 = kt * 64;
        if (kt < ktmax)
            asm volatile("cp.async.wait_group 1;" ::: "memory");
        else
            asm volatile("cp.async.wait_group 0;" ::: "memory");
        __syncthreads();
        if (kt + 2 <= ktmax) FL_ISSUE(kt + 2, (kt + 2) % 3);

        const int s = kt % 3;
        const uint32_t sKh = s0 + s * 32768;
        const uint32_t sKl = sKh + 8192;
        const uint32_t sVh = sKh + 16384;
        const uint32_t sVl = sKh + 24576;

        if (j0 <= rowmax) {
            // ---- S = Q K^T (3-term split) ----
            float sc[8][4];
#pragma unroll
            for (int nt = 0; nt < 8; nt++)
#pragma unroll
                for (int r = 0; r < 4; r++) sc[nt][r] = 0.f;
#pragma unroll
            for (int s4 = 0; s4 < 4; s4++) {
#pragma unroll
                for (int nt = 0; nt < 8; nt++) {
                    uint32_t bh[2], bl[2];
                    const int boff = SWZ128((nt * 8 + kRowL) * 128 + s4 * 32 + kHalf);
                    ldm_x2(bh, sKh + boff);
                    ldm_x2(bl, sKl + boff);
                    mma16816(sc[nt], qh[s4], bh);
                    mma16816(sc[nt], ql[s4], bh);
                    mma16816(sc[nt], qh[s4], bl);
                }
            }

            // ---- scale + causal mask ----
            if (j0 + 63 > warpmin) {
#pragma unroll
                for (int nt = 0; nt < 8; nt++) {
                    const int c0 = j0 + nt * 8 + cpair;
                    sc[nt][0] = (c0     > rowg0) ? -1e30f : sc[nt][0] * SCALE_F;
                    sc[nt][1] = (c0 + 1 > rowg0) ? -1e30f : sc[nt][1] * SCALE_F;
                    sc[nt][2] = (c0     > rowg1) ? -1e30f : sc[nt][2] * SCALE_F;
                    sc[nt][3] = (c0 + 1 > rowg1) ? -1e30f : sc[nt][3] * SCALE_F;
                }
            } else {
#pragma unroll
                for (int nt = 0; nt < 8; nt++)
#pragma unroll
                    for (int r = 0; r < 4; r++) sc[nt][r] *= SCALE_F;
            }

            // ---- online softmax ----
            float ml0 = -1e30f, ml1 = -1e30f;
#pragma unroll
            for (int nt = 0; nt < 8; nt++) {
                ml0 = fmaxf(ml0, fmaxf(sc[nt][0], sc[nt][1]));
                ml1 = fmaxf(ml1, fmaxf(sc[nt][2], sc[nt][3]));
            }
            ml0 = fmaxf(ml0, __shfl_xor_sync(0xffffffffu, ml0, 1));
            ml0 = fmaxf(ml0, __shfl_xor_sync(0xffffffffu, ml0, 2));
            ml1 = fmaxf(ml1, __shfl_xor_sync(0xffffffffu, ml1, 1));
            ml1 = fmaxf(ml1, __shfl_xor_sync(0xffffffffu, ml1, 2));
            const float mn0 = fmaxf(m0, ml0), mn1 = fmaxf(m1, ml1);
            const float a0 = __expf(m0 - mn0), a1 = __expf(m1 - mn1);
            m0 = mn0; m1 = mn1;
            float ps0 = 0.f, ps1 = 0.f;
#pragma unroll
            for (int nt = 0; nt < 8; nt++) {
                sc[nt][0] = __expf(sc[nt][0] - mn0); ps0 += sc[nt][0];
                sc[nt][1] = __expf(sc[nt][1] - mn0); ps0 += sc[nt][1];
                sc[nt][2] = __expf(sc[nt][2] - mn1); ps1 += sc[nt][2];
                sc[nt][3] = __expf(sc[nt][3] - mn1); ps1 += sc[nt][3];
            }
            ps0 += __shfl_xor_sync(0xffffffffu, ps0, 1);
            ps0 += __shfl_xor_sync(0xffffffffu, ps0, 2);
            ps1 += __shfl_xor_sync(0xffffffffu, ps1, 1);
            ps1 += __shfl_xor_sync(0xffffffffu, ps1, 2);
            l0 = l0 * a0 + ps0;
            l1 = l1 * a1 + ps1;
#pragma unroll
            for (int nt = 0; nt < 8; nt++) {
                out[nt][0] *= a0; out[nt][1] *= a0;
                out[nt][2] *= a1; out[nt][3] *= a1;
            }

            // ---- O += P V (3-term split) ----
#pragma unroll
            for (int s4 = 0; s4 < 4; s4++) {
                uint32_t ph[4], pl[4];
                {
                    const float p00 = sc[2 * s4][0],     p01 = sc[2 * s4][1];
                    const float p02 = sc[2 * s4][2],     p03 = sc[2 * s4][3];
                    const float p10 = sc[2 * s4 + 1][0], p11 = sc[2 * s4 + 1][1];
                    const float p12 = sc[2 * s4 + 1][2], p13 = sc[2 * s4 + 1][3];
                    ph[0] = packbf2(p00, p01);
                    ph[1] = packbf2(p02, p03);
                    ph[2] = packbf2(p10, p11);
                    ph[3] = packbf2(p12, p13);
                    pl[0] = packbf2(p00 - __bfloat162float(__float2bfloat16(p00)),
                                    p01 - __bfloat162float(__float2bfloat16(p01)));
                    pl[1] = packbf2(p02 - __bfloat162float(__float2bfloat16(p02)),
                                    p03 - __bfloat162float(__float2bfloat16(p03)));
                    pl[2] = packbf2(p10 - __bfloat162float(__float2bfloat16(p10)),
                                    p11 - __bfloat162float(__float2bfloat16(p11)));
                    pl[3] = packbf2(p12 - __bfloat162float(__float2bfloat16(p12)),
                                    p13 - __bfloat162float(__float2bfloat16(p13)));
                }
#pragma unroll
                for (int nt = 0; nt < 8; nt++) {
                    uint32_t vh[2], vl[2];
                    const int voff = SWZ128((16 * s4 + vRowL) * 128 + nt * 16);
                    ldm_x2t(vh, sVh + voff);
                    ldm_x2t(vl, sVl + voff);
                    mma16816(out[nt], ph, vh);
                    mma16816(out[nt], ph, vl);
                    mma16816(out[nt], pl, vh);
                }
            }
        }
    }
#undef FL_ISSUE

    const float inv0 = 1.0f / l0, inv1 = 1.0f / l1;
#pragma unroll
    for (int nt = 0; nt < 8; nt++) {
        const int col = h * 64 + nt * 8 + cpair;
        *(float2*)(attn + ((size_t)b * TT + rowg0) * DD + col) =
            make_float2(out[nt][0] * inv0, out[nt][1] * inv0);
        *(float2*)(attn + ((size_t)b * TT + rowg1) * DD + col) =
            make_float2(out[nt][2] * inv1, out[nt][3] * inv1);
    }
}

// ---------------------------------------------------------------------------
// KNN memory attention + gated combine + bf16 round-trip -> split planes.
// ---------------------------------------------------------------------------
__global__ __launch_bounds__(256) void mem_combine_split_kernel(
    const float* __restrict__ q, const float* __restrict__ attn,
    const float* __restrict__ mem_bank, const int* __restrict__ knn_idx,
    const float* __restrict__ gate, __nv_bfloat16* __restrict__ Y) {
    const int bt = blockIdx.x;
    const int b = bt / TT;
    const int tid = threadIdx.x;
    const int h = tid >> 4, s16 = tid & 15;
    const int off = h * HDIM + s16 * 4;

    float4 q4 = *(const float4*)(q + (size_t)bt * DD + off);

    int idxs[KNN];
#pragma unroll
    for (int kk = 0; kk < KNN; kk++) idxs[kk] = knn_idx[bt * KNN + kk];

    float logit[KNN];
#pragma unroll
    for (int kk = 0; kk < KNN; kk++) {
        const float* mk = mem_bank + (((size_t)b * MM + idxs[kk]) * 2 + 0) * DD + off;
        float4 m4 = *(const float4*)mk;
        float d = q4.x * m4.x + q4.y * m4.y + q4.z * m4.z + q4.w * m4.w;
        d += __shfl_xor_sync(0xffffffffu, d, 1);
        d += __shfl_xor_sync(0xffffffffu, d, 2);
        d += __shfl_xor_sync(0xffffffffu, d, 4);
        d += __shfl_xor_sync(0xffffffffu, d, 8);
        logit[kk] = d * SCALE_F;
    }
    float m = fmaxf(logit[0], fmaxf(logit[1], logit[2]));
    float w0 = __expf(logit[0] - m);
    float w1 = __expf(logit[1] - m);
    float w2 = __expf(logit[2] - m);
    const float inv = 1.0f / (w0 + w1 + w2);
    w0 *= inv; w1 *= inv; w2 *= inv;
    const float wk[KNN] = {w0, w1, w2};

    float4 acc = {0.f, 0.f, 0.f, 0.f};
#pragma unroll
    for (int kk = 0; kk < KNN; kk++) {
        const float* mv = mem_bank + (((size_t)b * MM + idxs[kk]) * 2 + 1) * DD + off;
        float4 m4 = *(const float4*)mv;
        acc.x = fmaf(wk[kk], m4.x, acc.x);
        acc.y = fmaf(wk[kk], m4.y, acc.y);
        acc.z = fmaf(wk[kk], m4.z, acc.z);
        acc.w = fmaf(wk[kk], m4.w, acc.w);
    }

    const float g = gate[h];
    const float gi = 1.0f - g;
    float4 a4 = *(const float4*)(attn + (size_t)bt * DD + off);
    float cv[4];
    cv[0] = __bfloat162float(__float2bfloat16(acc.x * g + a4.x * gi));
    cv[1] = __bfloat162float(__float2bfloat16(acc.y * g + a4.y * gi));
    cv[2] = __bfloat162float(__float2bfloat16(acc.z * g + a4.z * gi));
    cv[3] = __bfloat162float(__float2bfloat16(acc.w * g + a4.w * gi));

    __nv_bfloat16 hi[4], lo[4];
#pragma unroll
    for (int i = 0; i < 4; i++) {
        hi[i] = __float2bfloat16(cv[i]);
        lo[i] = __float2bfloat16(cv[i] - __bfloat162float(hi[i]));
    }
    __nv_bfloat16* y = Y + (size_t)bt * K3 + off;
    *(uint2*)y = *(const uint2*)hi;
    *(uint2*)(y + 1024) = *(const uint2*)hi;
    *(uint2*)(y + 2048) = *(const uint2*)lo;
}

// ---------------------------------------------------------------------------
extern "C" void kernel_launch(void* const* d_in, const int* in_sizes, int n_in,
                              void* d_out, int out_size) {
    const float* x    = (const float*)d_in[0];
    const float* Wq   = (const float*)d_in[1];
    const float* bq   = (const float*)d_in[2];
    const float* Wk   = (const float*)d_in[3];
    const float* bk   = (const float*)d_in[4];
    const float* Wv   = (const float*)d_in[5];
    const float* bv   = (const float*)d_in[6];
    const float* Wo   = (const float*)d_in[7];
    const float* bo   = (const float*)d_in[8];
    const float* gate = (const float*)d_in[9];
    const float* memb = (const float*)d_in[10];
    const int*   knn  = (const int*)d_in[11];
    float* out = (float*)d_out;

    float *q, *k, *v, *attn;
    __nv_bfloat16 *x2, *wqkv, *qs, *ks, *vs;
    cudaGetSymbolAddress((void**)&q, g_q);
    cudaGetSymbolAddress((void**)&k, g_k);
    cudaGetSymbolAddress((void**)&v, g_v);
    cudaGetSymbolAddress((void**)&attn, g_attn);
    cudaGetSymbolAddress((void**)&x2, g_x2);
    cudaGetSymbolAddress((void**)&wqkv, g_wqkv);
    cudaGetSymbolAddress((void**)&qs, g_qs);
    cudaGetSymbolAddress((void**)&ks, g_ks);
    cudaGetSymbolAddress((void**)&vs, g_vs);

    cudaFuncSetAttribute(flash_mma_kernel,
                         cudaFuncAttributeMaxDynamicSharedMemorySize, FLM_SMEM);
    cudaFuncSetAttribute(gemm_mma_kernel,
                         cudaFuncAttributeMaxDynamicSharedMemorySize, GEMM_SMEM);

    // one-shot split of x and all four weight matrices
    split_all_kernel<<<32768, 256>>>(x, Wq, Wk, Wv, Wo, x2, wqkv);

    // fused QKV GEMM: grid (24, 32)
    gemm_mma_kernel<<<dim3(24, NROWS / 128), 256, GEMM_SMEM>>>(
        x2, wqkv, bq, bk, bv, q, k, v);

    // fused normalize+split of q/k/v
    norm_split_kernel<<<dim3(NROWS, 3), 256>>>(q, k, v, qs, ks, vs);

    flash_mma_kernel<<<dim3(16, HH, BB), 256, FLM_SMEM>>>(qs, ks, vs, attn);

    // fused KNN combine + split (writes x2 directly)
    mem_combine_split_kernel<<<NROWS, 256>>>(q, attn, memb, knn, gate, x2);

    // O projection (Wo in slot 3 of the split-weight buffer)
    gemm_mma_kernel<<<dim3(8, NROWS / 128), 256, GEMM_SMEM>>>(
        x2, wqkv + (size_t)3 * DD * K3, bo, bo, bo, out, out, out);
}